// round 7
// baseline (speedup 1.0000x reference)
#include <cuda_runtime.h>
#include <cstdint>

#define N_MAX 50000
#define E_MAX 800000
#define IN_DIM 128
#define HEADS 4
#define OUT_DIM 32
#define OC (HEADS*OUT_DIM)   // 128
#define NEG_SLOPE 0.2f
#define EPS_F 1e-16f

// ---------------- scratch (no allocations allowed; 16B-aligned) ----------------
__device__ __align__(16) float g_h[N_MAX * OC];          // 25.6 MB
__device__ __align__(16) float g_asrc[N_MAX * HEADS];
__device__ __align__(16) float g_adst[N_MAX * HEADS];
__device__ __align__(16) float g_s[N_MAX * HEADS];
__device__ int g_idx64;   // 1 if edge_index is int64, 0 if int32

// ---------------- helpers ----------------
__device__ __forceinline__ void red_add_v4(float* p, float4 v) {
    asm volatile("red.global.add.v4.f32 [%0], {%1,%2,%3,%4};"
                 :: "l"(p), "f"(v.x), "f"(v.y), "f"(v.z), "f"(v.w) : "memory");
}
__device__ __forceinline__ void red_add_f(float* p, float v) {
    asm volatile("red.global.add.f32 [%0], %1;" :: "l"(p), "f"(v) : "memory");
}
__device__ __forceinline__ float lrelu(float a) {
    return a > 0.f ? a : NEG_SLOPE * a;
}
__device__ __forceinline__ int2 load_edge(const void* ei, int e, int eidx) {
    if (g_idx64) {
        const long long* p = (const long long*)ei;
        return make_int2((int)p[eidx], (int)p[e + eidx]);
    } else {
        const int* p = (const int*)ei;
        return make_int2(p[eidx], p[e + eidx]);
    }
}

// ---------------- K-1: detect edge_index dtype ----------------
__global__ void k_detect(const unsigned* __restrict__ raw) {
    unsigned any = 0;
    for (int i = threadIdx.x; i < 128; i += 32) any |= raw[2 * i + 1];
#pragma unroll
    for (int o = 16; o > 0; o >>= 1) any |= __shfl_down_sync(0xffffffffu, any, o);
    if (threadIdx.x == 0) g_idx64 = (any == 0u) ? 1 : 0;
}

// ---------------- K0: zero accumulators ----------------
__global__ void k_init(float* __restrict__ out, int n) {
    int idx = blockIdx.x * blockDim.x + threadIdx.x;
    if (idx < n * (OC / 4)) *(float4*)&out[idx * 4] = make_float4(0.f, 0.f, 0.f, 0.f);
    if (idx < n * HEADS) g_s[idx] = 0.f;
}

// ---------------- K1: h = x @ W^T + fused attention projections ----------------
#define TM 64
#define WS_S 132
#define XS_S 68
__global__ void k_gemm(const float* __restrict__ x, const float* __restrict__ W,
                       const float* __restrict__ att_src, const float* __restrict__ att_dst,
                       int n) {
    extern __shared__ float sm[];
    float* ws = sm;                 // 128*132
    float* xs = sm + IN_DIM * WS_S; // 128*68
    int tid = threadIdx.x;
    int tx = tid & 15, ty = tid >> 4;
    int row0 = blockIdx.x * TM;

    for (int idx = tid; idx < OC * IN_DIM; idx += 256) {
        int c = idx >> 7, k = idx & 127;
        ws[k * WS_S + c] = W[idx];
    }
    for (int idx = tid; idx < TM * IN_DIM; idx += 256) {
        int r = idx >> 7, k = idx & 127;
        int row = row0 + r;
        xs[k * XS_S + r] = (row < n) ? x[row * IN_DIM + k] : 0.f;
    }
    __syncthreads();

    float acc[4][8];
#pragma unroll
    for (int i = 0; i < 4; i++)
#pragma unroll
        for (int j = 0; j < 8; j++) acc[i][j] = 0.f;

#pragma unroll 8
    for (int k = 0; k < IN_DIM; k++) {
        float4 a  = *(const float4*)&xs[k * XS_S + ty * 4];
        float4 b0 = *(const float4*)&ws[k * WS_S + tx * 8];
        float4 b1 = *(const float4*)&ws[k * WS_S + tx * 8 + 4];
        float av[4] = {a.x, a.y, a.z, a.w};
        float bv[8] = {b0.x, b0.y, b0.z, b0.w, b1.x, b1.y, b1.z, b1.w};
#pragma unroll
        for (int i = 0; i < 4; i++)
#pragma unroll
            for (int j = 0; j < 8; j++) acc[i][j] = fmaf(av[i], bv[j], acc[i][j]);
    }

#pragma unroll
    for (int i = 0; i < 4; i++) {
        int row = row0 + ty * 4 + i;
        if (row < n) {
            *(float4*)&g_h[row * OC + tx * 8]     = make_float4(acc[i][0], acc[i][1], acc[i][2], acc[i][3]);
            *(float4*)&g_h[row * OC + tx * 8 + 4] = make_float4(acc[i][4], acc[i][5], acc[i][6], acc[i][7]);
        }
    }

    // ---- fused attention projection epilogue ----
    __syncthreads();                       // smem reuse
    float* rs = sm;                        // [64][16]
    float* rd = sm + TM * 16;              // [64][16]
    float as_[8], ad_[8];
#pragma unroll
    for (int j = 0; j < 8; j++) {
        as_[j] = att_src[tx * 8 + j];
        ad_[j] = att_dst[tx * 8 + j];
    }
#pragma unroll
    for (int i = 0; i < 4; i++) {
        float ps = 0.f, pd = 0.f;
#pragma unroll
        for (int j = 0; j < 8; j++) {
            ps = fmaf(acc[i][j], as_[j], ps);
            pd = fmaf(acc[i][j], ad_[j], pd);
        }
        rs[(ty * 4 + i) * 16 + tx] = ps;
        rd[(ty * 4 + i) * 16 + tx] = pd;
    }
    __syncthreads();
    int r = tid >> 2, hd = tid & 3;        // 256 threads = 64 rows x 4 heads
    int row = row0 + r;
    if (row < n) {
        float s = 0.f, d = 0.f;
#pragma unroll
        for (int t = 0; t < 4; t++) {
            s += rs[r * 16 + hd * 4 + t];
            d += rd[r * 16 + hd * 4 + t];
        }
        g_asrc[row * HEADS + hd] = s;
        g_adst[row * HEADS + hd] = d;
    }
}

// ---------------- K2: single edge pass — scatter ex*h and ex (one warp per edge) ----------------
__global__ void k_edgeA(const void* __restrict__ ei, float* __restrict__ out, int e) {
    int gtid = blockIdx.x * blockDim.x + threadIdx.x;
    int eidx = gtid >> 5;
    if (eidx >= e) return;
    int lane = threadIdx.x & 31;
    int2 sd = load_edge(ei, e, eidx);
    int hd = lane >> 3;

    float a  = g_asrc[sd.x * HEADS + hd] + g_adst[sd.y * HEADS + hd];
    float ex = __expf(lrelu(a));

    float4 v = *(const float4*)&g_h[sd.x * OC + lane * 4];
    v.x *= ex; v.y *= ex; v.z *= ex; v.w *= ex;
    red_add_v4(&out[sd.y * OC + lane * 4], v);

    if ((lane & 7) == 0) red_add_f(&g_s[sd.y * HEADS + hd], ex);
}

// ---------------- K3: normalize + bias ----------------
__global__ void k_norm(const float* __restrict__ bias, float* __restrict__ out, int n) {
    int idx = blockIdx.x * blockDim.x + threadIdx.x;   // over n * OC/4
    if (idx >= n * (OC / 4)) return;
    int node = idx >> 5;           // OC/4 = 32 float4s per node
    int c4 = idx & 31;
    int hd = c4 >> 3;
    float inv = 1.f / (g_s[node * HEADS + hd] + EPS_F);
    float4 v = *(float4*)&out[idx * 4];
    float4 b = *(const float4*)&bias[c4 * 4];
    v.x = fmaf(v.x, inv, b.x);
    v.y = fmaf(v.y, inv, b.y);
    v.z = fmaf(v.z, inv, b.z);
    v.w = fmaf(v.w, inv, b.w);
    *(float4*)&out[idx * 4] = v;
}

// ---------------- K4: pooled alpha (one thread per edge) ----------------
__global__ void k_pooled(const void* __restrict__ ei, float* __restrict__ pooled, int e) {
    int eidx = blockIdx.x * blockDim.x + threadIdx.x;
    if (eidx >= e) return;
    int2 sd = load_edge(ei, e, eidx);
    float4 as = *(const float4*)&g_asrc[sd.x * HEADS];
    float4 ad = *(const float4*)&g_adst[sd.y * HEADS];
    float4 sv = *(const float4*)&g_s[sd.y * HEADS];
    float p = __expf(lrelu(as.x + ad.x)) / (sv.x + EPS_F)
            + __expf(lrelu(as.y + ad.y)) / (sv.y + EPS_F)
            + __expf(lrelu(as.z + ad.z)) / (sv.z + EPS_F)
            + __expf(lrelu(as.w + ad.w)) / (sv.w + EPS_F);
    pooled[eidx] = p * 0.25f;
}

// ---------------- launch ----------------
extern "C" void kernel_launch(void* const* d_in, const int* in_sizes, int n_in,
                              void* d_out, int out_size) {
    const float* x       = (const float*)d_in[0];
    const void*  ei      = d_in[1];
    const float* W       = (const float*)d_in[2];
    const float* att_src = (const float*)d_in[3];
    const float* att_dst = (const float*)d_in[4];
    const float* bias    = (const float*)d_in[5];

    int n = in_sizes[0] / IN_DIM;
    int e = in_sizes[1] / 2;

    float* out    = (float*)d_out;
    float* pooled = (float*)d_out + (size_t)n * OC;

    int smem = (IN_DIM * WS_S + IN_DIM * XS_S) * sizeof(float);  // ~100 KB
    cudaFuncSetAttribute(k_gemm, cudaFuncAttributeMaxDynamicSharedMemorySize, smem);

    k_detect<<<1, 32>>>((const unsigned*)ei);
    k_init<<<(n * (OC / 4) + 255) / 256, 256>>>(out, n);
    k_gemm<<<(n + TM - 1) / TM, 256, smem>>>(x, W, att_src, att_dst, n);
    k_edgeA<<<(int)(((size_t)e * 32 + 255) / 256), 256>>>(ei, out, e);
    k_norm<<<(n * (OC / 4) + 255) / 256, 256>>>(bias, out, n);
    k_pooled<<<(e + 255) / 256, 256>>>(ei, pooled, e);
}

// round 8
// speedup vs baseline: 1.6171x; 1.6171x over previous
#include <cuda_runtime.h>
#include <cstdint>

#define N_MAX 50000
#define E_MAX 800000
#define IN_DIM 128
#define HEADS 4
#define OUT_DIM 32
#define OC (HEADS*OUT_DIM)   // 128
#define NEG_SLOPE 0.2f
#define EPS_F 1e-16f

// ---------------- scratch (no allocations allowed; 16B-aligned) ----------------
__device__ __align__(16) float g_h[N_MAX * OC];          // 25.6 MB
__device__ __align__(16) float g_asrc[N_MAX * HEADS];
__device__ __align__(16) float g_adst[N_MAX * HEADS];
__device__ __align__(16) float g_s[N_MAX * HEADS];
__device__ __align__(16) int   g_deg[N_MAX];
__device__ __align__(16) int   g_cur[N_MAX];
__device__ __align__(16) int   g_off[N_MAX + 1];
__device__ __align__(16) int   g_csr_src[E_MAX];         // src node per CSR slot
__device__ int g_idx64;   // 1 if edge_index is int64, 0 if int32

// ---------------- helpers ----------------
__device__ __forceinline__ float lrelu(float a) {
    return a > 0.f ? a : NEG_SLOPE * a;
}
__device__ __forceinline__ int2 load_edge(const void* ei, int e, int eidx) {
    if (g_idx64) {
        const long long* p = (const long long*)ei;
        return make_int2((int)p[eidx], (int)p[e + eidx]);
    } else {
        const int* p = (const int*)ei;
        return make_int2(p[eidx], p[e + eidx]);
    }
}

// ---------------- K detect: edge_index dtype ----------------
__global__ void k_detect(const unsigned* __restrict__ raw) {
    unsigned any = 0;
    for (int i = threadIdx.x; i < 128; i += 32) any |= raw[2 * i + 1];
#pragma unroll
    for (int o = 16; o > 0; o >>= 1) any |= __shfl_down_sync(0xffffffffu, any, o);
    if (threadIdx.x == 0) g_idx64 = (any == 0u) ? 1 : 0;
}

// ---------------- K zero: counters ----------------
__global__ void k_zero(int n) {
    int idx = blockIdx.x * blockDim.x + threadIdx.x;
    if (idx < n) { g_deg[idx] = 0; g_cur[idx] = 0; }
}

// ---------------- K1: h = x @ W^T (fp32, smem-tiled; NO epilogue) ----------------
#define TM 64
#define WS_S 132
#define XS_S 68
__global__ void k_gemm(const float* __restrict__ x, const float* __restrict__ W, int n) {
    extern __shared__ float sm[];
    float* ws = sm;                 // 128*132
    float* xs = sm + IN_DIM * WS_S; // 128*68
    int tid = threadIdx.x;
    int tx = tid & 15, ty = tid >> 4;
    int row0 = blockIdx.x * TM;

    for (int idx = tid; idx < OC * IN_DIM; idx += 256) {
        int c = idx >> 7, k = idx & 127;
        ws[k * WS_S + c] = W[idx];
    }
    for (int idx = tid; idx < TM * IN_DIM; idx += 256) {
        int r = idx >> 7, k = idx & 127;
        int row = row0 + r;
        xs[k * XS_S + r] = (row < n) ? x[row * IN_DIM + k] : 0.f;
    }
    __syncthreads();

    float acc[4][8];
#pragma unroll
    for (int i = 0; i < 4; i++)
#pragma unroll
        for (int j = 0; j < 8; j++) acc[i][j] = 0.f;

#pragma unroll 8
    for (int k = 0; k < IN_DIM; k++) {
        float4 a  = *(const float4*)&xs[k * XS_S + ty * 4];
        float4 b0 = *(const float4*)&ws[k * WS_S + tx * 8];
        float4 b1 = *(const float4*)&ws[k * WS_S + tx * 8 + 4];
        float av[4] = {a.x, a.y, a.z, a.w};
        float bv[8] = {b0.x, b0.y, b0.z, b0.w, b1.x, b1.y, b1.z, b1.w};
#pragma unroll
        for (int i = 0; i < 4; i++)
#pragma unroll
            for (int j = 0; j < 8; j++) acc[i][j] = fmaf(av[i], bv[j], acc[i][j]);
    }

#pragma unroll
    for (int i = 0; i < 4; i++) {
        int row = row0 + ty * 4 + i;
        if (row < n) {
            *(float4*)&g_h[row * OC + tx * 8]     = make_float4(acc[i][0], acc[i][1], acc[i][2], acc[i][3]);
            *(float4*)&g_h[row * OC + tx * 8 + 4] = make_float4(acc[i][4], acc[i][5], acc[i][6], acc[i][7]);
        }
    }
}

// ---------------- K2: per-(node,head) attention projections ----------------
__global__ void k_attproj(const float* __restrict__ att_src,
                          const float* __restrict__ att_dst, int n) {
    int idx = blockIdx.x * blockDim.x + threadIdx.x;
    if (idx >= n * HEADS) return;
    int hd = idx & (HEADS - 1);
    int node = idx >> 2;
    const float4* hrow = (const float4*)&g_h[node * OC + hd * OUT_DIM];
    float ssum = 0.f, dsum = 0.f;
#pragma unroll
    for (int i = 0; i < OUT_DIM / 4; i++) {
        float4 hv = hrow[i];
        float4 sv = *(const float4*)&att_src[hd * OUT_DIM + i * 4];
        float4 dv = *(const float4*)&att_dst[hd * OUT_DIM + i * 4];
        ssum += hv.x * sv.x + hv.y * sv.y + hv.z * sv.z + hv.w * sv.w;
        dsum += hv.x * dv.x + hv.y * dv.y + hv.z * dv.z + hv.w * dv.w;
    }
    g_asrc[idx] = ssum;
    g_adst[idx] = dsum;
}

// ---------------- CSR build ----------------
__global__ void k_count(const void* __restrict__ ei, int e) {
    int eidx = blockIdx.x * blockDim.x + threadIdx.x;
    if (eidx >= e) return;
    int dst = (g_idx64) ? (int)((const long long*)ei)[e + eidx]
                        : ((const int*)ei)[e + eidx];
    atomicAdd(&g_deg[dst], 1);
}

__global__ void k_scan(int n) {   // single block, 1024 threads; exclusive scan of g_deg -> g_off
    __shared__ int warpsum[32];
    int tid = threadIdx.x;
    int chunk = (n + 1023) / 1024;
    int beg = tid * chunk;
    int end = min(beg + chunk, n);
    int s = 0;
    for (int i = beg; i < end; i++) s += g_deg[i];
    int lane = tid & 31, wid = tid >> 5;
    int v = s;
#pragma unroll
    for (int o = 1; o < 32; o <<= 1) {
        int t = __shfl_up_sync(0xffffffffu, v, o);
        if (lane >= o) v += t;
    }
    if (lane == 31) warpsum[wid] = v;
    __syncthreads();
    if (wid == 0) {
        int w = warpsum[lane];
#pragma unroll
        for (int o = 1; o < 32; o <<= 1) {
            int t = __shfl_up_sync(0xffffffffu, w, o);
            if (lane >= o) w += t;
        }
        warpsum[lane] = w;
    }
    __syncthreads();
    int base = ((wid > 0) ? warpsum[wid - 1] : 0) + (v - s);  // exclusive prefix for this thread
    int run = base;
    for (int i = beg; i < end; i++) { g_off[i] = run; run += g_deg[i]; }
    if (tid == 0) g_off[n] = warpsum[31];
}

__global__ void k_fill(const void* __restrict__ ei, int e) {
    int eidx = blockIdx.x * blockDim.x + threadIdx.x;
    if (eidx >= e) return;
    int2 sd = load_edge(ei, e, eidx);
    int pos = g_off[sd.y] + atomicAdd(&g_cur[sd.y], 1);
    g_csr_src[pos] = sd.x;
}

// ---------------- K agg: one warp per dst node, register accumulation, no atomics ----------------
__global__ void k_agg(const float* __restrict__ bias, float* __restrict__ out, int n) {
    int w = blockIdx.x * (blockDim.x >> 5) + (threadIdx.x >> 5);
    if (w >= n) return;
    int lane = threadIdx.x & 31;
    int hd = lane >> 3;

    int off = g_off[w];
    int deg = g_off[w + 1] - off;

    float ad = g_adst[w * HEADS + hd];
    float4 acc = make_float4(0.f, 0.f, 0.f, 0.f);
    float ssum = 0.f;

    int i = 0;
    for (; i + 1 < deg; i += 2) {
        int s0 = g_csr_src[off + i];
        int s1 = g_csr_src[off + i + 1];
        float ex0 = __expf(lrelu(g_asrc[s0 * HEADS + hd] + ad));
        float ex1 = __expf(lrelu(g_asrc[s1 * HEADS + hd] + ad));
        float4 v0 = *(const float4*)&g_h[s0 * OC + lane * 4];
        float4 v1 = *(const float4*)&g_h[s1 * OC + lane * 4];
        ssum += ex0 + ex1;
        acc.x = fmaf(ex0, v0.x, fmaf(ex1, v1.x, acc.x));
        acc.y = fmaf(ex0, v0.y, fmaf(ex1, v1.y, acc.y));
        acc.z = fmaf(ex0, v0.z, fmaf(ex1, v1.z, acc.z));
        acc.w = fmaf(ex0, v0.w, fmaf(ex1, v1.w, acc.w));
    }
    if (i < deg) {
        int s0 = g_csr_src[off + i];
        float ex0 = __expf(lrelu(g_asrc[s0 * HEADS + hd] + ad));
        float4 v0 = *(const float4*)&g_h[s0 * OC + lane * 4];
        ssum += ex0;
        acc.x = fmaf(ex0, v0.x, acc.x);
        acc.y = fmaf(ex0, v0.y, acc.y);
        acc.z = fmaf(ex0, v0.z, acc.z);
        acc.w = fmaf(ex0, v0.w, acc.w);
    }

    float inv = 1.f / (ssum + EPS_F);
    float4 b = *(const float4*)&bias[lane * 4];
    acc.x = fmaf(acc.x, inv, b.x);
    acc.y = fmaf(acc.y, inv, b.y);
    acc.z = fmaf(acc.z, inv, b.z);
    acc.w = fmaf(acc.w, inv, b.w);
    *(float4*)&out[w * OC + lane * 4] = acc;

    if ((lane & 7) == 0) g_s[w * HEADS + hd] = ssum;
}

// ---------------- K pooled: one thread per edge ----------------
__global__ void k_pooled(const void* __restrict__ ei, float* __restrict__ pooled, int e) {
    int eidx = blockIdx.x * blockDim.x + threadIdx.x;
    if (eidx >= e) return;
    int2 sd = load_edge(ei, e, eidx);
    float4 as = *(const float4*)&g_asrc[sd.x * HEADS];
    float4 ad = *(const float4*)&g_adst[sd.y * HEADS];
    float4 sv = *(const float4*)&g_s[sd.y * HEADS];
    float p = __expf(lrelu(as.x + ad.x)) / (sv.x + EPS_F)
            + __expf(lrelu(as.y + ad.y)) / (sv.y + EPS_F)
            + __expf(lrelu(as.z + ad.z)) / (sv.z + EPS_F)
            + __expf(lrelu(as.w + ad.w)) / (sv.w + EPS_F);
    pooled[eidx] = p * 0.25f;
}

// ---------------- launch ----------------
extern "C" void kernel_launch(void* const* d_in, const int* in_sizes, int n_in,
                              void* d_out, int out_size) {
    const float* x       = (const float*)d_in[0];
    const void*  ei      = d_in[1];
    const float* W       = (const float*)d_in[2];
    const float* att_src = (const float*)d_in[3];
    const float* att_dst = (const float*)d_in[4];
    const float* bias    = (const float*)d_in[5];

    int n = in_sizes[0] / IN_DIM;
    int e = in_sizes[1] / 2;

    float* out    = (float*)d_out;
    float* pooled = (float*)d_out + (size_t)n * OC;

    int smem = (IN_DIM * WS_S + IN_DIM * XS_S) * sizeof(float);  // ~100 KB
    cudaFuncSetAttribute(k_gemm, cudaFuncAttributeMaxDynamicSharedMemorySize, smem);

    k_detect<<<1, 32>>>((const unsigned*)ei);
    k_zero<<<(n + 255) / 256, 256>>>(n);
    k_gemm<<<(n + TM - 1) / TM, 256, smem>>>(x, W, n);
    k_attproj<<<(n * HEADS + 255) / 256, 256>>>(att_src, att_dst, n);
    k_count<<<(e + 255) / 256, 256>>>(ei, e);
    k_scan<<<1, 1024>>>(n);
    k_fill<<<(e + 255) / 256, 256>>>(ei, e);
    k_agg<<<(n + 7) / 8, 256>>>(bias, out, n);
    k_pooled<<<(e + 255) / 256, 256>>>(ei, pooled, e);
}